// round 2
// baseline (speedup 1.0000x reference)
#include <cuda_runtime.h>
#include <cuda_bf16.h>

#define BB 4
#define TT 2048
#define CC 1024
#define DD 64

// Scratch for projected Q and K (V == K per source bug). 2 MB each.
__device__ float g_Q[BB * TT * DD];
__device__ float g_K[BB * TT * DD];

// ---------------------------------------------------------------------------
// Projection: out[row][d] = sum_c x[row][c] * W[d][c]
// Grid: (8192/64, 2)  blockIdx.y: 0 -> W_Q/g_Q, 1 -> W_K/g_K
// 256 threads (16x16), 64x64 output tile, 4x4 micro-tile, K-chunks of 32.
// ---------------------------------------------------------------------------
__global__ __launch_bounds__(256) void proj_kernel(
    const float* __restrict__ x,
    const float* __restrict__ Wq,
    const float* __restrict__ Wk)
{
    __shared__ float Xs[64 * 33];
    __shared__ float Ws[64 * 33];

    const float* W = blockIdx.y ? Wk : Wq;
    float* out = blockIdx.y ? g_K : g_Q;
    const int r0 = blockIdx.x * 64;
    const int t  = threadIdx.x;
    const int tx = t & 15;        // 0..15 -> output cols tx + 16*j
    const int ty = t >> 4;        // 0..15 -> output rows ty*4 + i

    float acc[4][4] = {};

    for (int c0 = 0; c0 < CC; c0 += 32) {
        #pragma unroll
        for (int i = 0; i < 8; i++) {
            int e = t + i * 256;            // 0..2047
            int r = e >> 5, c = e & 31;
            Xs[r * 33 + c] = x[(r0 + r) * CC + c0 + c];
            Ws[r * 33 + c] = W[r * CC + c0 + c];
        }
        __syncthreads();
        #pragma unroll 8
        for (int kk = 0; kk < 32; kk++) {
            float a[4], b[4];
            #pragma unroll
            for (int i = 0; i < 4; i++) a[i] = Xs[(ty * 4 + i) * 33 + kk];
            #pragma unroll
            for (int j = 0; j < 4; j++) b[j] = Ws[(tx + 16 * j) * 33 + kk];
            #pragma unroll
            for (int i = 0; i < 4; i++)
                #pragma unroll
                for (int j = 0; j < 4; j++)
                    acc[i][j] += a[i] * b[j];
        }
        __syncthreads();
    }

    #pragma unroll
    for (int i = 0; i < 4; i++)
        #pragma unroll
        for (int j = 0; j < 4; j++)
            out[(r0 + ty * 4 + i) * DD + tx + 16 * j] = acc[i][j];
}

// ---------------------------------------------------------------------------
// Flash attention (fp32, online softmax). V == K (source bug).
// Block: 32 queries x full d=64.  Key tiles of 64.  128 threads (16x8).
// Thread (tx,ty): rows ty*4+i (i<4), cols tx+16*j (j<4) -- used for both
// the S tile (cols = keys) and the O tile (cols = d). Conflict-free with
// smem row stride 65.
// Grid: B * (T/32) = 256 blocks, issued longest-first.
// ---------------------------------------------------------------------------
__global__ __launch_bounds__(128) void attn_kernel(float* __restrict__ out)
{
    __shared__ float Qs[32 * 65];
    __shared__ float Ks[64 * 65];
    __shared__ float Ps[32 * 65];

    const int nQT  = TT / 32;                 // 64 query tiles per batch
    const int bid  = blockIdx.x;
    const int batch = bid % BB;
    const int qt   = nQT - 1 - (bid / BB);    // longest work first
    const int q0   = qt * 32;

    const int t  = threadIdx.x;
    const int tx = t & 15;
    const int ty = t >> 4;                    // 0..7 -> rows ty*4+i (0..31)

    const float scale = 0.03125f;             // 1/sqrt(1024)

    // Load Q tile, pre-scaled.
    #pragma unroll
    for (int i = 0; i < 16; i++) {
        int e = t + i * 128;                  // 0..2047
        int r = e >> 6, d = e & 63;
        Qs[r * 65 + d] = g_Q[(batch * TT + q0 + r) * DD + d] * scale;
    }

    float o[4][4] = {};
    float m[4], l[4];
    #pragma unroll
    for (int i = 0; i < 4; i++) { m[i] = -1e30f; l[i] = 0.0f; }

    const int nkt = (q0 + 31) / 64 + 1;       // key tiles needed (causal)

    for (int kt = 0; kt < nkt; kt++) {
        const int k0 = kt * 64;
        __syncthreads();                      // Q ready / prev O-phase done
        #pragma unroll
        for (int i = 0; i < 32; i++) {
            int e = t + i * 128;              // 0..4095
            int r = e >> 6, d = e & 63;
            Ks[r * 65 + d] = g_K[(batch * TT + k0 + r) * DD + d];
        }
        __syncthreads();

        // S = Qs * Ks^T  (already scaled via Q)
        float s[4][4] = {};
        #pragma unroll 8
        for (int kk = 0; kk < 64; kk++) {
            float a[4], b[4];
            #pragma unroll
            for (int i = 0; i < 4; i++) a[i] = Qs[(ty * 4 + i) * 65 + kk];
            #pragma unroll
            for (int j = 0; j < 4; j++) b[j] = Ks[(tx + 16 * j) * 65 + kk];
            #pragma unroll
            for (int i = 0; i < 4; i++)
                #pragma unroll
                for (int j = 0; j < 4; j++)
                    s[i][j] += a[i] * b[j];
        }

        // Causal mask: only the last key tile can contain keys > query row.
        if (k0 + 63 > q0) {
            #pragma unroll
            for (int i = 0; i < 4; i++) {
                int row = q0 + ty * 4 + i;
                #pragma unroll
                for (int j = 0; j < 4; j++) {
                    int col = k0 + tx + 16 * j;
                    if (col > row) s[i][j] = -1e30f;
                }
            }
        }

        // Online softmax per row (16-lane reductions across tx).
        #pragma unroll
        for (int i = 0; i < 4; i++) {
            float mx = s[i][0];
            #pragma unroll
            for (int j = 1; j < 4; j++) mx = fmaxf(mx, s[i][j]);
            #pragma unroll
            for (int w = 1; w < 16; w <<= 1)
                mx = fmaxf(mx, __shfl_xor_sync(0xffffffffu, mx, w));

            float mn = fmaxf(m[i], mx);
            float alpha = __expf(m[i] - mn);
            float rs = 0.0f;
            #pragma unroll
            for (int j = 0; j < 4; j++) {
                float p = __expf(s[i][j] - mn);
                s[i][j] = p;
                rs += p;
            }
            #pragma unroll
            for (int w = 1; w < 16; w <<= 1)
                rs += __shfl_xor_sync(0xffffffffu, rs, w);

            l[i] = l[i] * alpha + rs;
            m[i] = mn;
            #pragma unroll
            for (int j = 0; j < 4; j++) {
                o[i][j] *= alpha;
                Ps[(ty * 4 + i) * 65 + tx + 16 * j] = s[i][j];
            }
        }
        __syncthreads();

        // O += P @ V   (V = K tile; Ks[s][d])
        #pragma unroll 8
        for (int ss = 0; ss < 64; ss++) {
            float p[4], v[4];
            #pragma unroll
            for (int i = 0; i < 4; i++) p[i] = Ps[(ty * 4 + i) * 65 + ss];
            #pragma unroll
            for (int j = 0; j < 4; j++) v[j] = Ks[ss * 65 + tx + 16 * j];
            #pragma unroll
            for (int i = 0; i < 4; i++)
                #pragma unroll
                for (int j = 0; j < 4; j++)
                    o[i][j] += p[i] * v[j];
        }
    }

    #pragma unroll
    for (int i = 0; i < 4; i++) {
        float inv = 1.0f / l[i];
        #pragma unroll
        for (int j = 0; j < 4; j++)
            out[(batch * TT + q0 + ty * 4 + i) * DD + tx + 16 * j] = o[i][j] * inv;
    }
}

extern "C" void kernel_launch(void* const* d_in, const int* in_sizes, int n_in,
                              void* d_out, int out_size)
{
    const float* x  = (const float*)d_in[0];
    const float* Wq = (const float*)d_in[1];
    const float* Wk = (const float*)d_in[2];
    // d_in[3] (W_V) intentionally unused: reference computes V with W_K.

    dim3 pgrid(BB * TT / 64, 2);
    proj_kernel<<<pgrid, 256>>>(x, Wq, Wk);
    attn_kernel<<<BB * (TT / 32), 128>>>((float*)d_out);
}

// round 6
// speedup vs baseline: 1.2983x; 1.2983x over previous
#include <cuda_runtime.h>
#include <cuda_bf16.h>
#include <cstdint>

#define BB 4
#define TT 2048
#define CC 1024
#define DD 64

// Scratch for projected Q and K (V == K per source bug). 2 MB each.
__device__ float g_Q[BB * TT * DD];
__device__ float g_K[BB * TT * DD];

__device__ __forceinline__ uint32_t f2tf(float x) {
    uint32_t r;
    asm("cvt.rna.tf32.f32 %0, %1;" : "=r"(r) : "f"(x));
    return r;
}

__device__ __forceinline__ void mma8(float c[4], const uint32_t a[4],
                                     uint32_t b0, uint32_t b1) {
    asm volatile(
        "mma.sync.aligned.m16n8k8.row.col.f32.tf32.tf32.f32 "
        "{%0,%1,%2,%3},{%4,%5,%6,%7},{%8,%9},{%0,%1,%2,%3};"
        : "+f"(c[0]), "+f"(c[1]), "+f"(c[2]), "+f"(c[3])
        : "r"(a[0]), "r"(a[1]), "r"(a[2]), "r"(a[3]), "r"(b0), "r"(b1));
}

// ---------------------------------------------------------------------------
// Fused Q/K projection with tf32 mma, 3-term hi/lo split (~fp32 accuracy).
// Block: 64 x-rows -> Q[64x64] and K[64x64]. 256 threads = 8 warps.
// Warp w: half = w>>2 (0=Q,1=K), rows 16*(w&3), cols 0..63 of its half
// (8 m16n8 tiles). K-chunks of 32 (4 k-steps of 8).
// Smem stride 36 (= 4 mod 32) -> conflict-free fragment loads.
// ---------------------------------------------------------------------------
#define PSTR 36
__global__ __launch_bounds__(256) void proj_kernel(
    const float* __restrict__ x,
    const float* __restrict__ Wq,
    const float* __restrict__ Wk)
{
    __shared__ float Xs[64 * PSTR];
    __shared__ float Wh[128 * PSTR];
    __shared__ float Wl[128 * PSTR];

    const int t = threadIdx.x;
    const int w = t >> 5, lane = t & 31;
    const int g = lane >> 2, t4 = lane & 3;
    const int half = w >> 2;        // 0 -> Q, 1 -> K
    const int r0w = (w & 3) * 16;
    const int r0 = blockIdx.x * 64;

    float acc[8][4] = {};

    for (int c0 = 0; c0 < CC; c0 += 32) {
        __syncthreads();
        #pragma unroll
        for (int i = 0; i < 8; i++) {
            int e = t + i * 256, r = e >> 5, c = e & 31;
            Xs[r * PSTR + c] = x[(r0 + r) * CC + c0 + c];
        }
        #pragma unroll
        for (int i = 0; i < 8; i++) {
            int e = t + i * 256, r = e >> 5, c = e & 31;
            float v = Wq[r * CC + c0 + c];
            uint32_t h = f2tf(v);
            float hf = __uint_as_float(h);
            Wh[r * PSTR + c] = hf;
            Wl[r * PSTR + c] = __uint_as_float(f2tf(v - hf));
        }
        #pragma unroll
        for (int i = 0; i < 8; i++) {
            int e = t + i * 256, r = e >> 5, c = e & 31;
            float v = Wk[r * CC + c0 + c];
            uint32_t h = f2tf(v);
            float hf = __uint_as_float(h);
            Wh[(64 + r) * PSTR + c] = hf;
            Wl[(64 + r) * PSTR + c] = __uint_as_float(f2tf(v - hf));
        }
        __syncthreads();

        #pragma unroll
        for (int ks = 0; ks < 4; ks++) {
            const int kk = ks * 8;
            uint32_t ah[4], al[4];
            #pragma unroll
            for (int i = 0; i < 4; i++) {
                int rr = r0w + g + (i & 1) * 8;
                int cc = kk + t4 + (i >> 1) * 4;
                float v = Xs[rr * PSTR + cc];
                ah[i] = f2tf(v);
                al[i] = f2tf(v - __uint_as_float(ah[i]));
            }
            #pragma unroll
            for (int j = 0; j < 8; j++) {
                int wr = half * 64 + j * 8 + g;
                uint32_t bh0 = __float_as_uint(Wh[wr * PSTR + kk + t4]);
                uint32_t bh1 = __float_as_uint(Wh[wr * PSTR + kk + t4 + 4]);
                uint32_t bl0 = __float_as_uint(Wl[wr * PSTR + kk + t4]);
                uint32_t bl1 = __float_as_uint(Wl[wr * PSTR + kk + t4 + 4]);
                mma8(acc[j], ah, bh0, bh1);
                mma8(acc[j], ah, bl0, bl1);
                mma8(acc[j], al, bh0, bh1);
            }
        }
    }

    float* out = half ? g_K : g_Q;
    #pragma unroll
    for (int j = 0; j < 8; j++) {
        int col = j * 8 + t4 * 2;
        out[(r0 + r0w + g) * DD + col]         = acc[j][0];
        out[(r0 + r0w + g) * DD + col + 1]     = acc[j][1];
        out[(r0 + r0w + g + 8) * DD + col]     = acc[j][2];
        out[(r0 + r0w + g + 8) * DD + col + 1] = acc[j][3];
    }
}

// ---------------------------------------------------------------------------
// Flash attention with tf32 mma. V == K (source bug).
// Block: 64 queries, 128 threads = 4 warps; warp w owns rows w*16..w*16+15
// over the FULL 64-key width (8 m16n8 tiles) -> no cross-warp softmax.
// S = Qhi*Khi (1-pass tf32; only ~5e-5 absolute logit error).
// PV = 3-term hi/lo (P staged fp32 in smem, split at load; V = Khi+Klo).
// Grid: 128 blocks, longest-first for causal load balance.
// Smem stride 68 (= 4 mod 32).
// ---------------------------------------------------------------------------
#define ASTR 68
__global__ __launch_bounds__(128) void attn_kernel(float* __restrict__ out)
{
    extern __shared__ float sm[];
    float* Qh = sm;                  // [64][ASTR]
    float* Kh = sm + 64 * ASTR;
    float* Kl = sm + 2 * 64 * ASTR;
    float* Ps = sm + 3 * 64 * ASTR;

    const int t = threadIdx.x, w = t >> 5, lane = t & 31;
    const int g = lane >> 2, t4 = lane & 3;
    const int r0w = w * 16;
    const int bid = blockIdx.x;
    const int batch = bid & 3;
    const int qt = 31 - (bid >> 2);          // longest work first
    const int q0 = qt * 64;
    const float scale = 0.03125f;            // 1/sqrt(1024)

    // Stage Q (hi only, pre-scaled).
    #pragma unroll
    for (int i = 0; i < 32; i++) {
        int e = t + i * 128, r = e >> 6, d = e & 63;
        Qh[r * ASTR + d] =
            __uint_as_float(f2tf(g_Q[(batch * TT + q0 + r) * DD + d] * scale));
    }

    float o[8][4] = {};
    float m0 = -1e30f, m1 = -1e30f, l0 = 0.0f, l1 = 0.0f;

    for (int kt = 0; kt <= qt; kt++) {
        const int k0 = kt * 64;
        __syncthreads();                     // Q staged / prev PV done with K
        #pragma unroll
        for (int i = 0; i < 32; i++) {
            int e = t + i * 128, r = e >> 6, d = e & 63;
            float v = g_K[(batch * TT + k0 + r) * DD + d];
            uint32_t h = f2tf(v);
            float hf = __uint_as_float(h);
            Kh[r * ASTR + d] = hf;
            Kl[r * ASTR + d] = __uint_as_float(f2tf(v - hf));
        }
        __syncthreads();

        // S = Q * K^T (tf32 1-pass)
        float s[8][4] = {};
        #pragma unroll
        for (int ks = 0; ks < 8; ks++) {
            const int kk = ks * 8;
            uint32_t a[4];
            a[0] = __float_as_uint(Qh[(r0w + g) * ASTR + kk + t4]);
            a[1] = __float_as_uint(Qh[(r0w + g + 8) * ASTR + kk + t4]);
            a[2] = __float_as_uint(Qh[(r0w + g) * ASTR + kk + t4 + 4]);
            a[3] = __float_as_uint(Qh[(r0w + g + 8) * ASTR + kk + t4 + 4]);
            #pragma unroll
            for (int j = 0; j < 8; j++) {
                int kr = j * 8 + g;
                uint32_t b0 = __float_as_uint(Kh[kr * ASTR + kk + t4]);
                uint32_t b1 = __float_as_uint(Kh[kr * ASTR + kk + t4 + 4]);
                mma8(s[j], a, b0, b1);
            }
        }

        // Causal mask on the diagonal tile (k0 == q0).
        if (kt == qt) {
            #pragma unroll
            for (int j = 0; j < 8; j++) {
                int cc = j * 8 + t4 * 2;
                int lr0 = r0w + g, lr1 = lr0 + 8;
                if (cc     > lr0) s[j][0] = -1e30f;
                if (cc + 1 > lr0) s[j][1] = -1e30f;
                if (cc     > lr1) s[j][2] = -1e30f;
                if (cc + 1 > lr1) s[j][3] = -1e30f;
            }
        }

        // Online softmax: rows (r0w+g) and (r0w+g+8); reduce over 4 lanes.
        float mx0 = -1e30f, mx1 = -1e30f;
        #pragma unroll
        for (int j = 0; j < 8; j++) {
            mx0 = fmaxf(mx0, fmaxf(s[j][0], s[j][1]));
            mx1 = fmaxf(mx1, fmaxf(s[j][2], s[j][3]));
        }
        mx0 = fmaxf(mx0, __shfl_xor_sync(0xffffffffu, mx0, 1));
        mx0 = fmaxf(mx0, __shfl_xor_sync(0xffffffffu, mx0, 2));
        mx1 = fmaxf(mx1, __shfl_xor_sync(0xffffffffu, mx1, 1));
        mx1 = fmaxf(mx1, __shfl_xor_sync(0xffffffffu, mx1, 2));

        float nm0 = fmaxf(m0, mx0), nm1 = fmaxf(m1, mx1);
        float al0 = __expf(m0 - nm0), al1 = __expf(m1 - nm1);
        float rs0 = 0.0f, rs1 = 0.0f;
        #pragma unroll
        for (int j = 0; j < 8; j++) {
            s[j][0] = __expf(s[j][0] - nm0);
            s[j][1] = __expf(s[j][1] - nm0);
            s[j][2] = __expf(s[j][2] - nm1);
            s[j][3] = __expf(s[j][3] - nm1);
            rs0 += s[j][0] + s[j][1];
            rs1 += s[j][2] + s[j][3];
            int cc = j * 8 + t4 * 2;
            Ps[(r0w + g) * ASTR + cc]         = s[j][0];
            Ps[(r0w + g) * ASTR + cc + 1]     = s[j][1];
            Ps[(r0w + g + 8) * ASTR + cc]     = s[j][2];
            Ps[(r0w + g + 8) * ASTR + cc + 1] = s[j][3];
        }
        rs0 += __shfl_xor_sync(0xffffffffu, rs0, 1);
        rs0 += __shfl_xor_sync(0xffffffffu, rs0, 2);
        rs1 += __shfl_xor_sync(0xffffffffu, rs1, 1);
        rs1 += __shfl_xor_sync(0xffffffffu, rs1, 2);

        l0 = l0 * al0 + rs0;
        l1 = l1 * al1 + rs1;
        m0 = nm0;
        m1 = nm1;
        #pragma unroll
        for (int j = 0; j < 8; j++) {
            o[j][0] *= al0; o[j][1] *= al0;
            o[j][2] *= al1; o[j][3] *= al1;
        }
        __syncwarp();   // Ps visible within the warp (rows are warp-private)

        // O += P @ V (V = K tile), 3-term hi/lo.
        #pragma unroll
        for (int ks = 0; ks < 8; ks++) {
            const int kk = ks * 8;
            uint32_t ph[4], pl[4];
            #pragma unroll
            for (int i = 0; i < 4; i++) {
                int rr = r0w + g + (i & 1) * 8;
                int cc = kk + t4 + (i >> 1) * 4;
                float v = Ps[rr * ASTR + cc];
                ph[i] = f2tf(v);
                pl[i] = f2tf(v - __uint_as_float(ph[i]));
            }
            #pragma unroll
            for (int j = 0; j < 8; j++) {
                int nn = j * 8 + g;
                uint32_t bh0 = __float_as_uint(Kh[(kk + t4) * ASTR + nn]);
                uint32_t bh1 = __float_as_uint(Kh[(kk + t4 + 4) * ASTR + nn]);
                uint32_t bl0 = __float_as_uint(Kl[(kk + t4) * ASTR + nn]);
                uint32_t bl1 = __float_as_uint(Kl[(kk + t4 + 4) * ASTR + nn]);
                mma8(o[j], ph, bh0, bh1);
                mma8(o[j], ph, bl0, bl1);
                mma8(o[j], pl, bh0, bh1);
            }
        }
    }

    const float inv0 = 1.0f / l0, inv1 = 1.0f / l1;
    const int row0 = batch * TT + q0 + r0w + g;
    #pragma unroll
    for (int j = 0; j < 8; j++) {
        int col = j * 8 + t4 * 2;
        out[row0 * DD + col]           = o[j][0] * inv0;
        out[row0 * DD + col + 1]       = o[j][1] * inv0;
        out[(row0 + 8) * DD + col]     = o[j][2] * inv1;
        out[(row0 + 8) * DD + col + 1] = o[j][3] * inv1;
    }
}

extern "C" void kernel_launch(void* const* d_in, const int* in_sizes, int n_in,
                              void* d_out, int out_size)
{
    const float* x  = (const float*)d_in[0];
    const float* Wq = (const float*)d_in[1];
    const float* Wk = (const float*)d_in[2];
    // d_in[3] (W_V) intentionally unused: reference computes V with W_K.

    proj_kernel<<<BB * TT / 64, 256>>>(x, Wq, Wk);

    const int smem = 4 * 64 * ASTR * sizeof(float);   // 69632 B
    cudaFuncSetAttribute(attn_kernel,
                         cudaFuncAttributeMaxDynamicSharedMemorySize, smem);
    attn_kernel<<<BB * (TT / 64), 128, smem>>>((float*)d_out);
}

// round 10
// speedup vs baseline: 1.9218x; 1.4803x over previous
#include <cuda_runtime.h>
#include <cuda_bf16.h>
#include <cstdint>

#define BB 4
#define TT 2048
#define CC 1024
#define DD 64

// Scratch for projected Q and K (V == K per source bug). 2 MB each.
__device__ float g_Q[BB * TT * DD];
__device__ float g_K[BB * TT * DD];

__device__ __forceinline__ uint32_t f2tf(float x) {
    uint32_t r;
    asm("cvt.rna.tf32.f32 %0, %1;" : "=r"(r) : "f"(x));
    return r;
}
__device__ __forceinline__ float f2tff(float x) {
    return __uint_as_float(f2tf(x));
}

__device__ __forceinline__ void mma8(float c[4], const uint32_t a[4],
                                     uint32_t b0, uint32_t b1) {
    asm volatile(
        "mma.sync.aligned.m16n8k8.row.col.f32.tf32.tf32.f32 "
        "{%0,%1,%2,%3},{%4,%5,%6,%7},{%8,%9},{%0,%1,%2,%3};"
        : "+f"(c[0]), "+f"(c[1]), "+f"(c[2]), "+f"(c[3])
        : "r"(a[0]), "r"(a[1]), "r"(a[2]), "r"(a[3]), "r"(b0), "r"(b1));
}

// ---------------------------------------------------------------------------
// Fused Q/K projection, tf32 mma, 2-term split: (x_hi + x_lo) * W_hi.
// W_hi truncation adds ~1.2e-4 rel err; x carried at full precision.
// Block: 64 x-rows -> Q[64x64] and K[64x64]. 256 threads = 8 warps.
// Warp w: half = w>>2 (0=Q,1=K), rows 16*(w&3), cols 0..63 of its half.
// ---------------------------------------------------------------------------
#define PSTR 36
__global__ __launch_bounds__(256) void proj_kernel(
    const float* __restrict__ x,
    const float* __restrict__ Wq,
    const float* __restrict__ Wk)
{
    __shared__ float Xs[64 * PSTR];
    __shared__ float Wh[128 * PSTR];

    const int t = threadIdx.x;
    const int w = t >> 5, lane = t & 31;
    const int g = lane >> 2, t4 = lane & 3;
    const int half = w >> 2;        // 0 -> Q, 1 -> K
    const int r0w = (w & 3) * 16;
    const int r0 = blockIdx.x * 64;

    float acc[8][4] = {};

    for (int c0 = 0; c0 < CC; c0 += 32) {
        __syncthreads();
        // X tile 64x32 (fp32), float4 path
        #pragma unroll
        for (int i = 0; i < 2; i++) {
            int e = t + i * 256, r = e >> 3, c4 = e & 7;
            float4 v = *(const float4*)(x + (r0 + r) * CC + c0 + c4 * 4);
            *(float4*)(Xs + r * PSTR + c4 * 4) = v;
        }
        // W tiles 2 x 64x32 (hi only)
        #pragma unroll
        for (int i = 0; i < 2; i++) {
            int e = t + i * 256, r = e >> 3, c4 = e & 7;
            float4 v = *(const float4*)(Wq + r * CC + c0 + c4 * 4);
            v.x = f2tff(v.x); v.y = f2tff(v.y);
            v.z = f2tff(v.z); v.w = f2tff(v.w);
            *(float4*)(Wh + r * PSTR + c4 * 4) = v;
        }
        #pragma unroll
        for (int i = 0; i < 2; i++) {
            int e = t + i * 256, r = e >> 3, c4 = e & 7;
            float4 v = *(const float4*)(Wk + r * CC + c0 + c4 * 4);
            v.x = f2tff(v.x); v.y = f2tff(v.y);
            v.z = f2tff(v.z); v.w = f2tff(v.w);
            *(float4*)(Wh + (64 + r) * PSTR + c4 * 4) = v;
        }
        __syncthreads();

        #pragma unroll
        for (int ks = 0; ks < 4; ks++) {
            const int kk = ks * 8;
            uint32_t ah[4], al[4];
            #pragma unroll
            for (int i = 0; i < 4; i++) {
                int rr = r0w + g + (i & 1) * 8;
                int cc = kk + t4 + (i >> 1) * 4;
                float v = Xs[rr * PSTR + cc];
                ah[i] = f2tf(v);
                al[i] = f2tf(v - __uint_as_float(ah[i]));
            }
            #pragma unroll
            for (int j = 0; j < 8; j++) {
                int wr = half * 64 + j * 8 + g;
                uint32_t bh0 = __float_as_uint(Wh[wr * PSTR + kk + t4]);
                uint32_t bh1 = __float_as_uint(Wh[wr * PSTR + kk + t4 + 4]);
                mma8(acc[j], ah, bh0, bh1);
                mma8(acc[j], al, bh0, bh1);
            }
        }
    }

    float* out = half ? g_K : g_Q;
    #pragma unroll
    for (int j = 0; j < 8; j++) {
        int col = j * 8 + t4 * 2;
        float2 v0 = { acc[j][0], acc[j][1] };
        float2 v1 = { acc[j][2], acc[j][3] };
        *(float2*)(out + (r0 + r0w + g) * DD + col)     = v0;
        *(float2*)(out + (r0 + r0w + g + 8) * DD + col) = v1;
    }
}

// ---------------------------------------------------------------------------
// Flash attention, tf32 mma. V == K (source bug).
// Block: 32 queries x 128-key tiles, 128 threads = 4 warps.
// Warp w: rowHalf h = w&1 (rows h*16..h*16+15), keyHalf kh = w>>1
// (keys kh*64..kh*64+63). Softmax stats combined across the warp pair via
// smem; partial O summed once at the end. Grid: 256 blocks, longest-first.
// S = Q_hi*K_hi (1-pass tf32). PV = (P_hi+P_lo)*V_hi.
// ---------------------------------------------------------------------------
#define ASTR 68
__global__ __launch_bounds__(128) void attn_kernel(float* __restrict__ out)
{
    extern __shared__ float sm[];
    float* Qh = sm;                        // [32][68]
    float* Kh = Qh + 32 * ASTR;            // [128][68]
    float* Ps = Kh + 128 * ASTR;           // 4 warps x [16][68] (warp-private)
    float* mxbuf = Ps + 64 * ASTR;         // [2][32]
    float* rsbuf = mxbuf + 64;             // [2][32]
    float* Obuf = Ps;                      // reuse after mainloop: [32][68]

    const int t = threadIdx.x, w = t >> 5, lane = t & 31;
    const int g = lane >> 2, t4 = lane & 3;
    const int h  = w & 1;                  // row half
    const int kh = w >> 1;                 // key half
    const int r0w = h * 16;
    const int bid = blockIdx.x;
    const int batch = bid & 3;
    const int qt = 63 - (bid >> 2);        // longest work first
    const int q0 = qt * 32;
    const int qlast = q0 + 31;
    const float scale = 0.03125f;          // 1/sqrt(1024)

    // Stage Q (hi only, pre-scaled): 32x64 via float4.
    {
        const float4* src = (const float4*)(g_Q + (batch * TT + q0) * DD);
        #pragma unroll
        for (int i = 0; i < 4; i++) {
            int e = t + i * 128, r = e >> 4, c4 = e & 15;
            float4 v = src[r * 16 + c4];
            v.x = f2tff(v.x * scale); v.y = f2tff(v.y * scale);
            v.z = f2tff(v.z * scale); v.w = f2tff(v.w * scale);
            *(float4*)(Qh + r * ASTR + c4 * 4) = v;
        }
    }

    float o[8][4] = {};
    float m0 = -1e30f, m1 = -1e30f, l0 = 0.0f, l1 = 0.0f;

    const int nkt = (q0 + 32 + 127) >> 7;

    for (int kt = 0; kt < nkt; kt++) {
        const int k0 = kt << 7;
        __syncthreads();                   // prev PV done with Kh
        // Stage K tile 128x64 (hi only), float4.
        {
            const float4* src = (const float4*)(g_K + (batch * TT + k0) * DD);
            #pragma unroll
            for (int i = 0; i < 16; i++) {
                int e = t + i * 128, r = e >> 4, c4 = e & 15;
                float4 v = src[r * 16 + c4];
                v.x = f2tff(v.x); v.y = f2tff(v.y);
                v.z = f2tff(v.z); v.w = f2tff(v.w);
                *(float4*)(Kh + r * ASTR + c4 * 4) = v;
            }
        }
        __syncthreads();

        const bool lastTile = (kt == nkt - 1);
        const int kwbase = k0 + kh * 64;   // this warp's first key
        const bool dead = lastTile && (kwbase > qlast);

        float s[8][4];
        float mx0 = -1e30f, mx1 = -1e30f;
        if (!dead) {
            #pragma unroll
            for (int j = 0; j < 8; j++)
                s[j][0] = s[j][1] = s[j][2] = s[j][3] = 0.0f;
            #pragma unroll
            for (int ks = 0; ks < 8; ks++) {
                const int kk = ks * 8;
                uint32_t a[4];
                a[0] = __float_as_uint(Qh[(r0w + g) * ASTR + kk + t4]);
                a[1] = __float_as_uint(Qh[(r0w + g + 8) * ASTR + kk + t4]);
                a[2] = __float_as_uint(Qh[(r0w + g) * ASTR + kk + t4 + 4]);
                a[3] = __float_as_uint(Qh[(r0w + g + 8) * ASTR + kk + t4 + 4]);
                #pragma unroll
                for (int j = 0; j < 8; j++) {
                    int kr = kh * 64 + j * 8 + g;
                    uint32_t b0 = __float_as_uint(Kh[kr * ASTR + kk + t4]);
                    uint32_t b1 = __float_as_uint(Kh[kr * ASTR + kk + t4 + 4]);
                    mma8(s[j], a, b0, b1);
                }
            }
            if (lastTile) {
                #pragma unroll
                for (int j = 0; j < 8; j++) {
                    int cc = kwbase + j * 8 + t4 * 2;
                    int lr0 = q0 + r0w + g, lr1 = lr0 + 8;
                    if (cc     > lr0) s[j][0] = -1e30f;
                    if (cc + 1 > lr0) s[j][1] = -1e30f;
                    if (cc     > lr1) s[j][2] = -1e30f;
                    if (cc + 1 > lr1) s[j][3] = -1e30f;
                }
            }
            #pragma unroll
            for (int j = 0; j < 8; j++) {
                mx0 = fmaxf(mx0, fmaxf(s[j][0], s[j][1]));
                mx1 = fmaxf(mx1, fmaxf(s[j][2], s[j][3]));
            }
            mx0 = fmaxf(mx0, __shfl_xor_sync(0xffffffffu, mx0, 1));
            mx0 = fmaxf(mx0, __shfl_xor_sync(0xffffffffu, mx0, 2));
            mx1 = fmaxf(mx1, __shfl_xor_sync(0xffffffffu, mx1, 1));
            mx1 = fmaxf(mx1, __shfl_xor_sync(0xffffffffu, mx1, 2));
        }
        if (t4 == 0) {
            mxbuf[kh * 32 + r0w + g]     = mx0;
            mxbuf[kh * 32 + r0w + 8 + g] = mx1;
        }
        __syncthreads();
        float nm0 = fmaxf(m0, fmaxf(mx0, mxbuf[(kh ^ 1) * 32 + r0w + g]));
        float nm1 = fmaxf(m1, fmaxf(mx1, mxbuf[(kh ^ 1) * 32 + r0w + 8 + g]));
        float al0 = __expf(m0 - nm0), al1 = __expf(m1 - nm1);

        float rs0 = 0.0f, rs1 = 0.0f;
        if (!dead) {
            float* Pw = Ps + w * 16 * ASTR;
            #pragma unroll
            for (int j = 0; j < 8; j++) {
                s[j][0] = __expf(s[j][0] - nm0);
                s[j][1] = __expf(s[j][1] - nm0);
                s[j][2] = __expf(s[j][2] - nm1);
                s[j][3] = __expf(s[j][3] - nm1);
                rs0 += s[j][0] + s[j][1];
                rs1 += s[j][2] + s[j][3];
                int cc = j * 8 + t4 * 2;
                float2 v0 = { s[j][0], s[j][1] };
                float2 v1 = { s[j][2], s[j][3] };
                *(float2*)(Pw + g * ASTR + cc)       = v0;
                *(float2*)(Pw + (8 + g) * ASTR + cc) = v1;
            }
            rs0 += __shfl_xor_sync(0xffffffffu, rs0, 1);
            rs0 += __shfl_xor_sync(0xffffffffu, rs0, 2);
            rs1 += __shfl_xor_sync(0xffffffffu, rs1, 1);
            rs1 += __shfl_xor_sync(0xffffffffu, rs1, 2);
        }
        if (t4 == 0) {
            rsbuf[kh * 32 + r0w + g]     = rs0;
            rsbuf[kh * 32 + r0w + 8 + g] = rs1;
        }
        __syncthreads();
        l0 = l0 * al0 + rs0 + rsbuf[(kh ^ 1) * 32 + r0w + g];
        l1 = l1 * al1 + rs1 + rsbuf[(kh ^ 1) * 32 + r0w + 8 + g];
        m0 = nm0; m1 = nm1;
        #pragma unroll
        for (int j = 0; j < 8; j++) {
            o[j][0] *= al0; o[j][1] *= al0;
            o[j][2] *= al1; o[j][3] *= al1;
        }

        if (!dead) {
            // O_partial += P(key half) @ V(key half rows); P split hi/lo.
            float* Pw = Ps + w * 16 * ASTR;
            #pragma unroll
            for (int ks = 0; ks < 8; ks++) {
                const int kk = ks * 8;
                uint32_t ph[4], pl[4];
                #pragma unroll
                for (int i = 0; i < 4; i++) {
                    int rr = g + (i & 1) * 8;
                    int cc = kk + t4 + (i >> 1) * 4;
                    float v = Pw[rr * ASTR + cc];
                    ph[i] = f2tf(v);
                    pl[i] = f2tf(v - __uint_as_float(ph[i]));
                }
                #pragma unroll
                for (int j = 0; j < 8; j++) {
                    int nn = j * 8 + g;
                    uint32_t b0 = __float_as_uint(Kh[(kh * 64 + kk + t4) * ASTR + nn]);
                    uint32_t b1 = __float_as_uint(Kh[(kh * 64 + kk + t4 + 4) * ASTR + nn]);
                    mma8(o[j], ph, b0, b1);
                    mma8(o[j], pl, b0, b1);
                }
            }
        }
    }

    // Combine partial O across the key-half warp pair.
    __syncthreads();                       // all PV reads of Ps done
    if (kh == 1) {
        #pragma unroll
        for (int j = 0; j < 8; j++) {
            int cc = j * 8 + t4 * 2;
            float2 v0 = { o[j][0], o[j][1] };
            float2 v1 = { o[j][2], o[j][3] };
            *(float2*)(Obuf + (r0w + g) * ASTR + cc)     = v0;
            *(float2*)(Obuf + (r0w + 8 + g) * ASTR + cc) = v1;
        }
    }
    __syncthreads();
    if (kh == 0) {
        const float inv0 = 1.0f / l0, inv1 = 1.0f / l1;
        const int row0 = batch * TT + q0 + r0w + g;
        #pragma unroll
        for (int j = 0; j < 8; j++) {
            int cc = j * 8 + t4 * 2;
            float2 p0 = *(const float2*)(Obuf + (r0w + g) * ASTR + cc);
            float2 p1 = *(const float2*)(Obuf + (r0w + 8 + g) * ASTR + cc);
            float2 v0 = { (o[j][0] + p0.x) * inv0, (o[j][1] + p0.y) * inv0 };
            float2 v1 = { (o[j][2] + p1.x) * inv1, (o[j][3] + p1.y) * inv1 };
            *(float2*)(out + row0 * DD + cc)        = v0;
            *(float2*)(out + (row0 + 8) * DD + cc)  = v1;
        }
    }
}

extern "C" void kernel_launch(void* const* d_in, const int* in_sizes, int n_in,
                              void* d_out, int out_size)
{
    const float* x  = (const float*)d_in[0];
    const float* Wq = (const float*)d_in[1];
    const float* Wk = (const float*)d_in[2];
    // d_in[3] (W_V) intentionally unused: reference computes V with W_K.

    proj_kernel<<<BB * TT / 64, 256>>>(x, Wq, Wk);

    const int smem = (32 + 128 + 64) * ASTR * sizeof(float) + 2 * 64 * sizeof(float);
    cudaFuncSetAttribute(attn_kernel,
                         cudaFuncAttributeMaxDynamicSharedMemorySize, smem);
    attn_kernel<<<BB * (TT / 32), 128, smem>>>((float*)d_out);
}